// round 2
// baseline (speedup 1.0000x reference)
#include <cuda_runtime.h>
#include <math.h>

#define BATCH 128
#define SEQ 176
#define DIN 20
#define DMODEL 256
#define DINNER 256
#define DX2 512
#define MROWS (BATCH*SEQ)   /* 22528 */
#define DSTATE 4
#define DTRANK 16
#define EPSF 1e-5f

// ---------------- scratch (static device globals; no allocation) ----------------
__device__ __align__(16) float g_xln[MROWS*DMODEL];
__device__ __align__(16) float g_xz [MROWS*DX2];
__device__ __align__(16) float g_xc [MROWS*DINNER];
__device__ __align__(16) float g_dbl[MROWS*24];
__device__ __align__(16) float g_dt [MROWS*DINNER];
__device__ __align__(16) float g_y  [MROWS*DINNER];
__device__ __align__(16) float g_h2 [MROWS*DINNER];
__device__ __align__(16) float g_a1 [MROWS*128];
__device__ __align__(16) float g_a2 [MROWS*64];
__device__ __align__(16) float g_a3 [MROWS*16];

// ---------------- kernel 1: lin1 + bn1(eval) + leaky_relu + layernorm ----------------
__global__ __launch_bounds__(256)
void k_front(const float* __restrict__ x,
             const float* __restrict__ w, const float* __restrict__ b,
             const float* __restrict__ bn_g, const float* __restrict__ bn_b,
             const float* __restrict__ ln_g, const float* __restrict__ ln_b) {
    int row = blockIdx.x;          // b*SEQ + l
    int l   = row % SEQ;
    int c   = threadIdx.x;         // 0..255 output channel
    __shared__ float xs[DIN];
    __shared__ float red[8];
    __shared__ float s_mu, s_rstd;
    if (c < DIN) xs[c] = x[row*DIN + c];
    __syncthreads();
    float acc = b[c];
    const float* wc = w + c*DIN;
    #pragma unroll
    for (int k = 0; k < DIN; k++) acc = fmaf(xs[k], wc[k], acc);
    float scale = bn_g[l] * rsqrtf(1.0f + EPSF);
    acc = acc * scale + bn_b[l];
    acc = acc >= 0.f ? acc : 0.01f * acc;     // leaky relu
    // layernorm over 256
    float v = acc;
    float s = v;
    #pragma unroll
    for (int o = 16; o > 0; o >>= 1) s += __shfl_xor_sync(0xffffffffu, s, o);
    int wid = c >> 5, lid = c & 31;
    if (lid == 0) red[wid] = s;
    __syncthreads();
    if (c < 8) {
        float t = red[c];
        #pragma unroll
        for (int o = 4; o > 0; o >>= 1) t += __shfl_xor_sync(0xffu, t, o);
        if (c == 0) s_mu = t * (1.0f/256.0f);
    }
    __syncthreads();
    float mu = s_mu;
    float d  = v - mu;
    float q  = d * d;
    #pragma unroll
    for (int o = 16; o > 0; o >>= 1) q += __shfl_xor_sync(0xffffffffu, q, o);
    if (lid == 0) red[wid] = q;
    __syncthreads();
    if (c < 8) {
        float t = red[c];
        #pragma unroll
        for (int o = 4; o > 0; o >>= 1) t += __shfl_xor_sync(0xffu, t, o);
        if (c == 0) s_rstd = rsqrtf(t * (1.0f/256.0f) + EPSF);
    }
    __syncthreads();
    g_xln[row*DMODEL + c] = d * s_rstd * ln_g[c] + ln_b[c];
}

// ---------------- generic fp32 GEMM: C[M,N] = A[M,K(lda)] @ W[N,K]^T (+epilogue) ----------------
enum { EPI_NONE = 0, EPI_BIAS = 1, EPI_BIAS_SOFTPLUS = 2, EPI_BN5 = 3 };

template<int EPI>
__global__ __launch_bounds__(256)
void k_gemm(const float* __restrict__ A, int lda,
            const float* __restrict__ W,
            const float* __restrict__ bias,
            const float* __restrict__ e1, const float* __restrict__ e2,
            float* __restrict__ C, int N, int K) {
    __shared__ float As[16][64];
    __shared__ float Ws[16][64];
    int tid = threadIdx.x;
    int tx = tid & 15, ty = tid >> 4;
    int row0 = blockIdx.y * 64, col0 = blockIdx.x * 64;
    int pm = tid >> 2;            // 0..63
    int pk = (tid & 3) * 4;       // 0,4,8,12
    float acc[4][4] = {};
    for (int k0 = 0; k0 < K; k0 += 16) {
        float4 av = make_float4(0.f,0.f,0.f,0.f);
        float4 wv = make_float4(0.f,0.f,0.f,0.f);
        if (k0 + pk < K)
            av = *(const float4*)(A + (size_t)(row0 + pm) * lda + k0 + pk);
        if (col0 + pm < N && k0 + pk < K)
            wv = *(const float4*)(W + (size_t)(col0 + pm) * K + k0 + pk);
        __syncthreads();
        As[pk  ][pm] = av.x; As[pk+1][pm] = av.y; As[pk+2][pm] = av.z; As[pk+3][pm] = av.w;
        Ws[pk  ][pm] = wv.x; Ws[pk+1][pm] = wv.y; Ws[pk+2][pm] = wv.z; Ws[pk+3][pm] = wv.w;
        __syncthreads();
        #pragma unroll
        for (int k = 0; k < 16; k++) {
            float4 a  = *(const float4*)&As[k][ty*4];
            float4 w4 = *(const float4*)&Ws[k][tx*4];
            acc[0][0] = fmaf(a.x, w4.x, acc[0][0]); acc[0][1] = fmaf(a.x, w4.y, acc[0][1]);
            acc[0][2] = fmaf(a.x, w4.z, acc[0][2]); acc[0][3] = fmaf(a.x, w4.w, acc[0][3]);
            acc[1][0] = fmaf(a.y, w4.x, acc[1][0]); acc[1][1] = fmaf(a.y, w4.y, acc[1][1]);
            acc[1][2] = fmaf(a.y, w4.z, acc[1][2]); acc[1][3] = fmaf(a.y, w4.w, acc[1][3]);
            acc[2][0] = fmaf(a.z, w4.x, acc[2][0]); acc[2][1] = fmaf(a.z, w4.y, acc[2][1]);
            acc[2][2] = fmaf(a.z, w4.z, acc[2][2]); acc[2][3] = fmaf(a.z, w4.w, acc[2][3]);
            acc[3][0] = fmaf(a.w, w4.x, acc[3][0]); acc[3][1] = fmaf(a.w, w4.y, acc[3][1]);
            acc[3][2] = fmaf(a.w, w4.z, acc[3][2]); acc[3][3] = fmaf(a.w, w4.w, acc[3][3]);
        }
    }
    const float bscale = rsqrtf(1.0f + EPSF);
    #pragma unroll
    for (int i = 0; i < 4; i++) {
        int r = row0 + ty*4 + i;
        #pragma unroll
        for (int j = 0; j < 4; j++) {
            int c = col0 + tx*4 + j;
            if (c < N) {
                float v = acc[i][j];
                if (EPI == EPI_BIAS) v += bias[c];
                if (EPI == EPI_BIAS_SOFTPLUS) {
                    v += bias[c];
                    v = fmaxf(v, 0.f) + log1pf(expf(-fabsf(v)));   // softplus, stable
                }
                if (EPI == EPI_BN5) {
                    int l = r % SEQ;
                    v = v * (e1[l] * bscale) + e2[l];
                }
                C[(size_t)r * N + c] = v;
            }
        }
    }
}

// ---------------- depthwise causal conv (k=2) + SiLU ----------------
__global__ __launch_bounds__(256)
void k_conv(const float* __restrict__ convw, const float* __restrict__ convb) {
    int idx = blockIdx.x * blockDim.x + threadIdx.x;
    if (idx >= MROWS * DINNER) return;
    int row = idx >> 8;
    int d   = idx & 255;
    int l   = row % SEQ;
    float u1 = g_xz[(size_t)row * DX2 + d];
    float u0 = (l > 0) ? g_xz[(size_t)(row - 1) * DX2 + d] : 0.f;
    float v  = fmaf(u0, __ldg(convw + 2*d), fmaf(u1, __ldg(convw + 2*d + 1), __ldg(convb + d)));
    g_xc[idx] = v / (1.f + __expf(-v));       // silu
}

// ---------------- selective scan: one thread per (batch, channel) ----------------
__global__ __launch_bounds__(256)
void k_scan(const float* __restrict__ A_log, const float* __restrict__ Dp) {
    int b = blockIdx.x;
    int d = threadIdx.x;
    float A0 = -expf(A_log[d*4+0]);
    float A1 = -expf(A_log[d*4+1]);
    float A2 = -expf(A_log[d*4+2]);
    float A3 = -expf(A_log[d*4+3]);
    float Dd = Dp[d];
    float h0 = 0.f, h1 = 0.f, h2 = 0.f, h3 = 0.f;
    for (int t = 0; t < SEQ; t++) {
        int row = b * SEQ + t;
        float dt = g_dt[(size_t)row * DINNER + d];
        float xc = g_xc[(size_t)row * DINNER + d];
        float z  = g_xz[(size_t)row * DX2 + DINNER + d];
        const float* bc = g_dbl + (size_t)row * 24 + DTRANK;
        float B0 = __ldg(bc+0), B1 = __ldg(bc+1), B2 = __ldg(bc+2), B3 = __ldg(bc+3);
        float C0 = __ldg(bc+4), C1 = __ldg(bc+5), C2 = __ldg(bc+6), C3 = __ldg(bc+7);
        float dtxc = dt * xc;
        h0 = fmaf(h0, __expf(dt * A0), dtxc * B0);
        h1 = fmaf(h1, __expf(dt * A1), dtxc * B1);
        h2 = fmaf(h2, __expf(dt * A2), dtxc * B2);
        h3 = fmaf(h3, __expf(dt * A3), dtxc * B3);
        float y = h0*C0 + h1*C1 + h2*C2 + h3*C3;
        y = fmaf(Dd, xc, y);
        float sz = z / (1.f + __expf(-z));
        g_y[(size_t)row * DINNER + d] = y * sz;
    }
}

// ---------------- fc3 + sigmoid: warp per (batch, out) ----------------
__global__ __launch_bounds__(480)
void k_fc3(const float* __restrict__ w, const float* __restrict__ b,
           float* __restrict__ out) {
    int bidx = blockIdx.x;
    int warp = threadIdx.x >> 5;
    int lane = threadIdx.x & 31;
    const float* in = g_a3 + (size_t)bidx * 2816;
    const float* wr = w + (size_t)warp * 2816;
    float s = 0.f;
    for (int k = lane; k < 2816; k += 32) s = fmaf(in[k], wr[k], s);
    #pragma unroll
    for (int o = 16; o > 0; o >>= 1) s += __shfl_xor_sync(0xffffffffu, s, o);
    if (lane == 0) {
        float v = s + b[warp];
        out[bidx * 15 + warp] = 1.f / (1.f + expf(-v));
    }
}

// ---------------- launch ----------------
extern "C" void kernel_launch(void* const* d_in, const int* in_sizes, int n_in,
                              void* d_out, int out_size) {
    const float* x         = (const float*)d_in[0];
    const float* lin1_w    = (const float*)d_in[1];
    const float* lin1_b    = (const float*)d_in[2];
    const float* bn1_g     = (const float*)d_in[3];
    const float* bn1_b     = (const float*)d_in[4];
    const float* ln_g      = (const float*)d_in[5];
    const float* ln_b      = (const float*)d_in[6];
    const float* in_proj_w = (const float*)d_in[7];
    const float* conv_w    = (const float*)d_in[8];
    const float* conv_b    = (const float*)d_in[9];
    const float* x_proj_w  = (const float*)d_in[10];
    const float* dt_proj_w = (const float*)d_in[11];
    const float* dt_proj_b = (const float*)d_in[12];
    const float* A_log     = (const float*)d_in[13];
    const float* Dp        = (const float*)d_in[14];
    const float* out_proj_w= (const float*)d_in[15];
    const float* bn5_g     = (const float*)d_in[16];
    const float* bn5_b     = (const float*)d_in[17];
    const float* l5a_w     = (const float*)d_in[18];
    const float* l5a_b     = (const float*)d_in[19];
    const float* l5b_w     = (const float*)d_in[20];
    const float* l5b_b     = (const float*)d_in[21];
    const float* l5c_w     = (const float*)d_in[22];
    const float* l5c_b     = (const float*)d_in[23];
    const float* fc3_w     = (const float*)d_in[24];
    const float* fc3_b     = (const float*)d_in[25];

    float *p_xln, *p_xz, *p_xc, *p_dbl, *p_dt, *p_y, *p_h2, *p_a1, *p_a2, *p_a3;
    cudaGetSymbolAddress((void**)&p_xln, g_xln);
    cudaGetSymbolAddress((void**)&p_xz,  g_xz);
    cudaGetSymbolAddress((void**)&p_xc,  g_xc);
    cudaGetSymbolAddress((void**)&p_dbl, g_dbl);
    cudaGetSymbolAddress((void**)&p_dt,  g_dt);
    cudaGetSymbolAddress((void**)&p_y,   g_y);
    cudaGetSymbolAddress((void**)&p_h2,  g_h2);
    cudaGetSymbolAddress((void**)&p_a1,  g_a1);
    cudaGetSymbolAddress((void**)&p_a2,  g_a2);
    cudaGetSymbolAddress((void**)&p_a3,  g_a3);

    const int GY = MROWS / 64;   // 352

    // 1. front: lin1 + bn1 + leaky relu + layernorm
    k_front<<<MROWS, 256>>>(x, lin1_w, lin1_b, bn1_g, bn1_b, ln_g, ln_b);

    // 2. in_proj: [M,256] @ [512,256]^T -> [M,512]
    k_gemm<EPI_NONE><<<dim3(512/64, GY), 256>>>(p_xln, DMODEL, in_proj_w,
                                                nullptr, nullptr, nullptr, p_xz, DX2, DMODEL);

    // 3. conv + silu
    k_conv<<<(MROWS*DINNER + 255)/256, 256>>>(conv_w, conv_b);

    // 4. x_proj: [M,256] @ [24,256]^T -> [M,24]
    k_gemm<EPI_NONE><<<dim3(1, GY), 256>>>(p_xc, DINNER, x_proj_w,
                                           nullptr, nullptr, nullptr, p_dbl, 24, DINNER);

    // 5. dt: [M,16(lda=24)] @ [256,16]^T + b -> softplus -> [M,256]
    k_gemm<EPI_BIAS_SOFTPLUS><<<dim3(256/64, GY), 256>>>(p_dbl, 24, dt_proj_w,
                                           dt_proj_b, nullptr, nullptr, p_dt, DINNER, DTRANK);

    // 6. selective scan (+ D skip + silu(z) gate)
    k_scan<<<BATCH, DINNER>>>(A_log, Dp);

    // 7. out_proj + bn5
    k_gemm<EPI_BN5><<<dim3(256/64, GY), 256>>>(p_y, DINNER, out_proj_w,
                                           nullptr, bn5_g, bn5_b, p_h2, DMODEL, DINNER);

    // 8-10. head MLP
    k_gemm<EPI_BIAS><<<dim3(2, GY), 256>>>(p_h2, DMODEL, l5a_w, l5a_b, nullptr, nullptr, p_a1, 128, 256);
    k_gemm<EPI_BIAS><<<dim3(1, GY), 256>>>(p_a1, 128,   l5b_w, l5b_b, nullptr, nullptr, p_a2, 64, 128);
    k_gemm<EPI_BIAS><<<dim3(1, GY), 256>>>(p_a2, 64,    l5c_w, l5c_b, nullptr, nullptr, p_a3, 16, 64);

    // 11. fc3 + sigmoid
    k_fc3<<<BATCH, 480>>>(fc3_w, fc3_b, (float*)d_out);
}

// round 4
// speedup vs baseline: 1.3350x; 1.3350x over previous
#include <cuda_runtime.h>
#include <cuda_bf16.h>
#include <math.h>
#include <stdint.h>

#define BATCH 128
#define SEQ 176
#define DIN 20
#define DMODEL 256
#define DINNER 256
#define DX2 512
#define MROWS (BATCH*SEQ)   /* 22528 = 176*128 */
#define DSTATE 4
#define DTRANK 16
#define EPSF 1e-5f

// ---------------- scratch ----------------
__device__ __align__(16) float g_xln[MROWS*DMODEL];
__device__ __align__(16) float g_xz [MROWS*DX2];
__device__ __align__(16) float g_xc [MROWS*DINNER];
__device__ __align__(16) float g_dbl[MROWS*24];
__device__ __align__(16) float g_dt [MROWS*DINNER];
__device__ __align__(16) float g_y  [MROWS*DINNER];
__device__ __align__(16) float g_h2 [MROWS*DINNER];
__device__ __align__(16) float g_a1 [MROWS*128];
__device__ __align__(16) float g_a2 [MROWS*64];
__device__ __align__(16) float g_a3 [MROWS*16];

// ================= mma.sync helpers =================
__device__ __forceinline__ uint32_t smem_u32(const void* p) {
    uint32_t a;
    asm("{ .reg .u64 t; cvta.to.shared.u64 t, %1; cvt.u32.u64 %0, t; }" : "=r"(a) : "l"(p));
    return a;
}
__device__ __forceinline__ void ldsm_x4(uint32_t addr, uint32_t* r) {
    asm volatile("ldmatrix.sync.aligned.m8n8.x4.shared.b16 {%0,%1,%2,%3}, [%4];"
        : "=r"(r[0]),"=r"(r[1]),"=r"(r[2]),"=r"(r[3]) : "r"(addr));
}
__device__ __forceinline__ void ldsm_x4_t(uint32_t addr, uint32_t* r) {
    asm volatile("ldmatrix.sync.aligned.m8n8.x4.trans.shared.b16 {%0,%1,%2,%3}, [%4];"
        : "=r"(r[0]),"=r"(r[1]),"=r"(r[2]),"=r"(r[3]) : "r"(addr));
}
__device__ __forceinline__ void mma_bf16(float* c, const uint32_t* a, const uint32_t* b) {
    asm volatile("mma.sync.aligned.m16n8k16.row.col.f32.bf16.bf16.f32 "
        "{%0,%1,%2,%3}, {%4,%5,%6,%7}, {%8,%9}, {%0,%1,%2,%3};"
        : "+f"(c[0]),"+f"(c[1]),"+f"(c[2]),"+f"(c[3])
        : "r"(a[0]),"r"(a[1]),"r"(a[2]),"r"(a[3]), "r"(b[0]),"r"(b[1]));
}
__device__ __forceinline__ void split1(float v, __nv_bfloat16& h, __nv_bfloat16& l) {
    h = __float2bfloat16_rn(v);
    l = __float2bfloat16_rn(v - __bfloat162float(h));
}

enum { EPI_NONE = 0, EPI_BIAS = 1, EPI_BIAS_SOFTPLUS = 2, EPI_BN5 = 3 };

// ---------------- tensor-core GEMM: C[M,N] = A[M,K(lda)] @ W[N,K]^T (+epilogue) ----------------
// CTA tile: 128 x (32*WN). Split bf16: hi*hi + hi*lo + lo*hi, fp32 accum.
template<int WN, int EPI>
__global__ __launch_bounds__(128*WN)
void k_mma(const float* __restrict__ A, int lda,
           const float* __restrict__ W,
           const float* __restrict__ bias,
           const float* __restrict__ e1, const float* __restrict__ e2,
           float* __restrict__ C, int N, int K) {
    constexpr int NT = 32 * WN;
    constexpr int KC = 32;
    constexpr int SA = KC + 8;    // A row stride (bf16)
    constexpr int SB = NT + 8;    // B row stride (bf16)
    __shared__ __align__(16) __nv_bfloat16 sAh[128*SA], sAl[128*SA];
    __shared__ __align__(16) __nv_bfloat16 sBh[KC*SB],  sBl[KC*SB];

    const int tid  = threadIdx.x;
    const int lane = tid & 31;
    const int wid  = tid >> 5;
    const int wm   = wid & 3;          // 4 warps along M
    const int wn   = wid >> 2;         // WN warps along N
    const int row0 = blockIdx.y * 128;
    const int col0 = blockIdx.x * NT;
    const int nthr = 128 * WN;

    float acc[2][4][4];
    #pragma unroll
    for (int a = 0; a < 2; a++)
        #pragma unroll
        for (int b = 0; b < 4; b++)
            #pragma unroll
            for (int c = 0; c < 4; c++) acc[a][b][c] = 0.f;

    const int nch = (K + KC - 1) / KC;
    for (int ci = 0; ci < nch; ci++) {
        const int k0c = ci * KC;
        // ---- stage A [128][KC] (m-major) hi/lo ----
        for (int i = tid; i < 128 * (KC/4); i += nthr) {
            int r = i / (KC/4), c4 = (i % (KC/4)) * 4;
            float v[4] = {0.f, 0.f, 0.f, 0.f};
            if (k0c + c4 + 4 <= K) {
                float4 t = *(const float4*)(A + (size_t)(row0 + r) * lda + k0c + c4);
                v[0]=t.x; v[1]=t.y; v[2]=t.z; v[3]=t.w;
            } else {
                #pragma unroll
                for (int j = 0; j < 4; j++)
                    if (k0c + c4 + j < K) v[j] = A[(size_t)(row0 + r) * lda + k0c + c4 + j];
            }
            #pragma unroll
            for (int j = 0; j < 4; j++)
                split1(v[j], sAh[r*SA + c4 + j], sAl[r*SA + c4 + j]);
        }
        // ---- stage B [KC][NT] (k-major, transposed from W[N][K]) hi/lo ----
        for (int i = tid; i < NT * (KC/4); i += nthr) {
            int r = i / (KC/4), c4 = (i % (KC/4)) * 4;   // r = n index, c4 = k offset
            float v[4] = {0.f, 0.f, 0.f, 0.f};
            if (col0 + r < N) {
                if (k0c + c4 + 4 <= K) {
                    float4 t = *(const float4*)(W + (size_t)(col0 + r) * K + k0c + c4);
                    v[0]=t.x; v[1]=t.y; v[2]=t.z; v[3]=t.w;
                } else {
                    #pragma unroll
                    for (int j = 0; j < 4; j++)
                        if (k0c + c4 + j < K) v[j] = W[(size_t)(col0 + r) * K + k0c + c4 + j];
                }
            }
            #pragma unroll
            for (int j = 0; j < 4; j++)
                split1(v[j], sBh[(c4 + j)*SB + r], sBl[(c4 + j)*SB + r]);
        }
        __syncthreads();

        // ---- MMAs over 2 k16 steps ----
        #pragma unroll
        for (int ks = 0; ks < KC/16; ks++) {
            const int kb = ks * 16;
            uint32_t ah[2][4], al[2][4];
            #pragma unroll
            for (int mi = 0; mi < 2; mi++) {
                int mb = wm*32 + mi*16;
                int r  = mb + (lane & 7) + ((lane & 8) ? 8 : 0);
                int kk = kb + ((lane & 16) ? 8 : 0);
                ldsm_x4(smem_u32(sAh + r*SA + kk), ah[mi]);
                ldsm_x4(smem_u32(sAl + r*SA + kk), al[mi]);
            }
            uint32_t bh[4][2], bl[4][2];
            #pragma unroll
            for (int np = 0; np < 2; np++) {       // each x4 covers 2 n-tiles (16 cols)
                int nb = wn*32 + np*16;
                int kk = kb + (lane & 7) + ((lane & 8) ? 8 : 0);
                int nn = nb + ((lane & 16) ? 8 : 0);
                uint32_t r4[4];
                ldsm_x4_t(smem_u32(sBh + kk*SB + nn), r4);
                bh[np*2][0]=r4[0]; bh[np*2][1]=r4[1]; bh[np*2+1][0]=r4[2]; bh[np*2+1][1]=r4[3];
                ldsm_x4_t(smem_u32(sBl + kk*SB + nn), r4);
                bl[np*2][0]=r4[0]; bl[np*2][1]=r4[1]; bl[np*2+1][0]=r4[2]; bl[np*2+1][1]=r4[3];
            }
            #pragma unroll
            for (int mi = 0; mi < 2; mi++)
                #pragma unroll
                for (int ni = 0; ni < 4; ni++) {
                    mma_bf16(acc[mi][ni], ah[mi], bh[ni]);   // hi*hi
                    mma_bf16(acc[mi][ni], ah[mi], bl[ni]);   // hi*lo
                    mma_bf16(acc[mi][ni], al[mi], bh[ni]);   // lo*hi
                }
        }
        __syncthreads();
    }

    // ---- epilogue ----
    const float bscale = rsqrtf(1.0f + EPSF);
    #pragma unroll
    for (int mi = 0; mi < 2; mi++) {
        #pragma unroll
        for (int ni = 0; ni < 4; ni++) {
            int r = row0 + wm*32 + mi*16 + (lane >> 2);
            int c = col0 + wn*32 + ni*8 + (lane & 3) * 2;
            #pragma unroll
            for (int half = 0; half < 2; half++) {
                int rr = r + half * 8;
                float v0 = acc[mi][ni][half*2 + 0];
                float v1 = acc[mi][ni][half*2 + 1];
                if (EPI == EPI_BIAS) { v0 += bias[c]; v1 += bias[c+1 < N ? c+1 : c]; }
                if (EPI == EPI_BIAS_SOFTPLUS) {
                    v0 += bias[c]; v1 += bias[c+1 < N ? c+1 : c];
                    v0 = fmaxf(v0, 0.f) + log1pf(expf(-fabsf(v0)));
                    v1 = fmaxf(v1, 0.f) + log1pf(expf(-fabsf(v1)));
                }
                if (EPI == EPI_BN5) {
                    int ll = rr % SEQ;
                    float sc = e1[ll] * bscale, sb = e2[ll];
                    v0 = v0 * sc + sb;
                    v1 = v1 * sc + sb;
                }
                float* crow = C + (size_t)rr * N;
                if (c + 1 < N)      *(float2*)(crow + c) = make_float2(v0, v1);
                else if (c < N)     crow[c] = v0;
            }
        }
    }
}

// ---------------- kernel: lin1 + bn1(eval) + leaky_relu + layernorm ----------------
__global__ __launch_bounds__(256)
void k_front(const float* __restrict__ x,
             const float* __restrict__ w, const float* __restrict__ b,
             const float* __restrict__ bn_g, const float* __restrict__ bn_b,
             const float* __restrict__ ln_g, const float* __restrict__ ln_b) {
    int row = blockIdx.x;
    int l   = row % SEQ;
    int c   = threadIdx.x;
    __shared__ float xs[DIN];
    __shared__ float red[8];
    __shared__ float s_mu, s_rstd;
    if (c < DIN) xs[c] = x[row*DIN + c];
    __syncthreads();
    float acc = b[c];
    const float* wc = w + c*DIN;
    #pragma unroll
    for (int k = 0; k < DIN; k++) acc = fmaf(xs[k], wc[k], acc);
    float scale = bn_g[l] * rsqrtf(1.0f + EPSF);
    acc = acc * scale + bn_b[l];
    acc = acc >= 0.f ? acc : 0.01f * acc;
    float v = acc;
    float s = v;
    #pragma unroll
    for (int o = 16; o > 0; o >>= 1) s += __shfl_xor_sync(0xffffffffu, s, o);
    int wid = c >> 5, lid = c & 31;
    if (lid == 0) red[wid] = s;
    __syncthreads();
    if (c < 8) {
        float t = red[c];
        #pragma unroll
        for (int o = 4; o > 0; o >>= 1) t += __shfl_xor_sync(0xffu, t, o);
        if (c == 0) s_mu = t * (1.0f/256.0f);
    }
    __syncthreads();
    float mu = s_mu;
    float d  = v - mu;
    float q  = d * d;
    #pragma unroll
    for (int o = 16; o > 0; o >>= 1) q += __shfl_xor_sync(0xffffffffu, q, o);
    if (lid == 0) red[wid] = q;
    __syncthreads();
    if (c < 8) {
        float t = red[c];
        #pragma unroll
        for (int o = 4; o > 0; o >>= 1) t += __shfl_xor_sync(0xffu, t, o);
        if (c == 0) s_rstd = rsqrtf(t * (1.0f/256.0f) + EPSF);
    }
    __syncthreads();
    g_xln[row*DMODEL + c] = d * s_rstd * ln_g[c] + ln_b[c];
}

// ---------------- depthwise causal conv (k=2) + SiLU ----------------
__global__ __launch_bounds__(256)
void k_conv(const float* __restrict__ convw, const float* __restrict__ convb) {
    int idx = blockIdx.x * blockDim.x + threadIdx.x;
    if (idx >= MROWS * DINNER) return;
    int row = idx >> 8;
    int d   = idx & 255;
    int l   = row % SEQ;
    float u1 = g_xz[(size_t)row * DX2 + d];
    float u0 = (l > 0) ? g_xz[(size_t)(row - 1) * DX2 + d] : 0.f;
    float v  = fmaf(u0, __ldg(convw + 2*d), fmaf(u1, __ldg(convw + 2*d + 1), __ldg(convb + d)));
    g_xc[idx] = v / (1.f + __expf(-v));
}

// ---------------- selective scan ----------------
__global__ __launch_bounds__(256)
void k_scan(const float* __restrict__ A_log, const float* __restrict__ Dp) {
    int b = blockIdx.x;
    int d = threadIdx.x;
    float A0 = -expf(A_log[d*4+0]);
    float A1 = -expf(A_log[d*4+1]);
    float A2 = -expf(A_log[d*4+2]);
    float A3 = -expf(A_log[d*4+3]);
    float Dd = Dp[d];
    float h0 = 0.f, h1 = 0.f, h2 = 0.f, h3 = 0.f;
    for (int t = 0; t < SEQ; t++) {
        int row = b * SEQ + t;
        float dt = g_dt[(size_t)row * DINNER + d];
        float xc = g_xc[(size_t)row * DINNER + d];
        float z  = g_xz[(size_t)row * DX2 + DINNER + d];
        const float* bc = g_dbl + (size_t)row * 24 + DTRANK;
        float B0 = __ldg(bc+0), B1 = __ldg(bc+1), B2 = __ldg(bc+2), B3 = __ldg(bc+3);
        float C0 = __ldg(bc+4), C1 = __ldg(bc+5), C2 = __ldg(bc+6), C3 = __ldg(bc+7);
        float dtxc = dt * xc;
        h0 = fmaf(h0, __expf(dt * A0), dtxc * B0);
        h1 = fmaf(h1, __expf(dt * A1), dtxc * B1);
        h2 = fmaf(h2, __expf(dt * A2), dtxc * B2);
        h3 = fmaf(h3, __expf(dt * A3), dtxc * B3);
        float y = h0*C0 + h1*C1 + h2*C2 + h3*C3;
        y = fmaf(Dd, xc, y);
        float sz = z / (1.f + __expf(-z));
        g_y[(size_t)row * DINNER + d] = y * sz;
    }
}

// ---------------- fc3 + sigmoid ----------------
__global__ __launch_bounds__(480)
void k_fc3(const float* __restrict__ w, const float* __restrict__ b,
           float* __restrict__ out) {
    int bidx = blockIdx.x;
    int warp = threadIdx.x >> 5;
    int lane = threadIdx.x & 31;
    const float* in = g_a3 + (size_t)bidx * 2816;
    const float* wr = w + (size_t)warp * 2816;
    float s = 0.f;
    for (int k = lane; k < 2816; k += 32) s = fmaf(in[k], wr[k], s);
    #pragma unroll
    for (int o = 16; o > 0; o >>= 1) s += __shfl_xor_sync(0xffffffffu, s, o);
    if (lane == 0) {
        float v = s + b[warp];
        out[bidx * 15 + warp] = 1.f / (1.f + expf(-v));
    }
}

// ---------------- launch ----------------
extern "C" void kernel_launch(void* const* d_in, const int* in_sizes, int n_in,
                              void* d_out, int out_size) {
    const float* x         = (const float*)d_in[0];
    const float* lin1_w    = (const float*)d_in[1];
    const float* lin1_b    = (const float*)d_in[2];
    const float* bn1_g     = (const float*)d_in[3];
    const float* bn1_b     = (const float*)d_in[4];
    const float* ln_g      = (const float*)d_in[5];
    const float* ln_b      = (const float*)d_in[6];
    const float* in_proj_w = (const float*)d_in[7];
    const float* conv_w    = (const float*)d_in[8];
    const float* conv_b    = (const float*)d_in[9];
    const float* x_proj_w  = (const float*)d_in[10];
    const float* dt_proj_w = (const float*)d_in[11];
    const float* dt_proj_b = (const float*)d_in[12];
    const float* A_log     = (const float*)d_in[13];
    const float* Dp        = (const float*)d_in[14];
    const float* out_proj_w= (const float*)d_in[15];
    const float* bn5_g     = (const float*)d_in[16];
    const float* bn5_b     = (const float*)d_in[17];
    const float* l5a_w     = (const float*)d_in[18];
    const float* l5a_b     = (const float*)d_in[19];
    const float* l5b_w     = (const float*)d_in[20];
    const float* l5b_b     = (const float*)d_in[21];
    const float* l5c_w     = (const float*)d_in[22];
    const float* l5c_b     = (const float*)d_in[23];
    const float* fc3_w     = (const float*)d_in[24];
    const float* fc3_b     = (const float*)d_in[25];

    float *p_xln, *p_xz, *p_xc, *p_dbl, *p_dt, *p_y, *p_h2, *p_a1, *p_a2, *p_a3;
    cudaGetSymbolAddress((void**)&p_xln, g_xln);
    cudaGetSymbolAddress((void**)&p_xz,  g_xz);
    cudaGetSymbolAddress((void**)&p_xc,  g_xc);
    cudaGetSymbolAddress((void**)&p_dbl, g_dbl);
    cudaGetSymbolAddress((void**)&p_dt,  g_dt);
    cudaGetSymbolAddress((void**)&p_y,   g_y);
    cudaGetSymbolAddress((void**)&p_h2,  g_h2);
    cudaGetSymbolAddress((void**)&p_a1,  g_a1);
    cudaGetSymbolAddress((void**)&p_a2,  g_a2);
    cudaGetSymbolAddress((void**)&p_a3,  g_a3);

    const int GY = MROWS / 128;   // 176

    // 1. front
    k_front<<<MROWS, 256>>>(x, lin1_w, lin1_b, bn1_g, bn1_b, ln_g, ln_b);

    // 2. in_proj: [M,256]@[512,256]^T
    k_mma<2, EPI_NONE><<<dim3(8, GY), 256>>>(p_xln, DMODEL, in_proj_w,
        nullptr, nullptr, nullptr, p_xz, DX2, DMODEL);

    // 3. conv + silu
    k_conv<<<(MROWS*DINNER + 255)/256, 256>>>(conv_w, conv_b);

    // 4. x_proj: [M,256]@[24,256]^T
    k_mma<1, EPI_NONE><<<dim3(1, GY), 128>>>(p_xc, DINNER, x_proj_w,
        nullptr, nullptr, nullptr, p_dbl, 24, DINNER);

    // 5. dt: [M,16(lda24)]@[256,16]^T + b -> softplus
    k_mma<2, EPI_BIAS_SOFTPLUS><<<dim3(4, GY), 256>>>(p_dbl, 24, dt_proj_w,
        dt_proj_b, nullptr, nullptr, p_dt, DINNER, DTRANK);

    // 6. scan
    k_scan<<<BATCH, DINNER>>>(A_log, Dp);

    // 7. out_proj + bn5
    k_mma<2, EPI_BN5><<<dim3(4, GY), 256>>>(p_y, DINNER, out_proj_w,
        nullptr, bn5_g, bn5_b, p_h2, DMODEL, DINNER);

    // 8-10. head MLP
    k_mma<2, EPI_BIAS><<<dim3(2, GY), 256>>>(p_h2, DMODEL, l5a_w,
        l5a_b, nullptr, nullptr, p_a1, 128, 256);
    k_mma<2, EPI_BIAS><<<dim3(1, GY), 256>>>(p_a1, 128, l5b_w,
        l5b_b, nullptr, nullptr, p_a2, 64, 128);
    k_mma<1, EPI_BIAS><<<dim3(1, GY), 128>>>(p_a2, 64, l5c_w,
        l5c_b, nullptr, nullptr, p_a3, 16, 64);

    // 11. fc3 + sigmoid
    k_fc3<<<BATCH, 480>>>(fc3_w, fc3_b, (float*)d_out);
}